// round 2
// baseline (speedup 1.0000x reference)
#include <cuda_runtime.h>

// Problem constants
#define BATCH 4
#define DD 128
#define HH 128
#define WW 128
#define SLICE (HH*WW)          // 16384
#define VOL   (DD*HH*WW)       // 2097152
#define VTOT  (BATCH*VOL)      // 8388608
#define WS 11
#define RAD 5

#define C1F 1.0e-4f            // 0.01^2
#define C2F 9.0e-4f            // 0.03^2

// Packed intermediates: (mu1,mu2) pairs, (E[x^2],E[y^2]) pairs, E[xy] scalar.
__device__ float2 g_mu [VTOT];
__device__ float2 g_cv [VTOT];
__device__ float  g_c12[VTOT];
__device__ float  g_w[WS];
__device__ double g_acc;
__device__ unsigned g_cnt;

// ---------------------------------------------------------------------------
// Packed f32x2 helpers (Blackwell fma.rn.f32x2 / mul.rn.f32x2)
// ---------------------------------------------------------------------------
__device__ __forceinline__ float2 ffma2(float2 a, float2 b, float2 c) {
    float2 d;
    asm("fma.rn.f32x2 %0, %1, %2, %3;"
        : "=l"(reinterpret_cast<unsigned long long&>(d))
        : "l"(reinterpret_cast<unsigned long long&>(a)),
          "l"(reinterpret_cast<unsigned long long&>(b)),
          "l"(reinterpret_cast<unsigned long long&>(c)));
    return d;
}
__device__ __forceinline__ float2 fmul2(float2 a, float2 b) {
    float2 d;
    asm("mul.rn.f32x2 %0, %1, %2;"
        : "=l"(reinterpret_cast<unsigned long long&>(d))
        : "l"(reinterpret_cast<unsigned long long&>(a)),
          "l"(reinterpret_cast<unsigned long long&>(b)));
    return d;
}

// ---------------------------------------------------------------------------
// K1: fused x-conv + y-conv over 32x32 tiles of one (b,z) slice.
// ---------------------------------------------------------------------------
#define TILE 32
#define IW   42   // TILE + 2*RAD
#define ABS  43   // sAB row stride (float2), odd -> conflict-friendly
#define INS  33   // intermediate row stride

__global__ __launch_bounds__(384, 2) void conv_xy_kernel(
    const float* __restrict__ img1, const float* __restrict__ img2,
    const float* __restrict__ window)
{
    __shared__ float2 sAB[IW][ABS];
    __shared__ float2 sMU[IW][INS];
    __shared__ float2 sCV[IW][INS];
    __shared__ float  sC12[IW][INS];
    __shared__ float  sw[WS];

    const int tid = threadIdx.x;
    const int tx = blockIdx.x, ty = blockIdx.y, bz = blockIdx.z; // bz = b*128+z
    const int x0 = tx * TILE - RAD;
    const int y0 = ty * TILE - RAD;
    const size_t base = (size_t)bz * SLICE;

    // Recover separable 1-D Gaussian: row sums of the 3-D window are exact.
    if (tid < WS) {
        float s = 0.f;
        #pragma unroll 11
        for (int j = 0; j < 121; ++j) s += __ldg(window + tid * 121 + j);
        sw[tid] = s;
        if (bz == 0 && tx == 0 && ty == 0) {
            g_w[tid] = s;
            if (tid == 0) g_acc = 0.0;   // graph-replay safe reset (K2 runs after K1)
        }
    }

    // Load 42x42 interleaved (a,b) halo tile.
    for (int i = tid; i < IW * IW; i += 384) {
        int yy = i / IW, xx = i - yy * IW;
        int gy = y0 + yy, gx = x0 + xx;
        float a = 0.f, b = 0.f;
        if ((unsigned)gy < HH && (unsigned)gx < WW) {
            size_t idx = base + (size_t)gy * WW + gx;
            a = __ldg(img1 + idx);
            b = __ldg(img2 + idx);
        }
        sAB[yy][xx] = make_float2(a, b);
    }
    __syncthreads();

    float w[WS]; float2 w2[WS];
    #pragma unroll
    for (int t = 0; t < WS; ++t) { w[t] = sw[t]; w2[t] = make_float2(w[t], w[t]); }

    // Stage 1: x-conv. 336 items (42 rows x 8 groups of 4 outputs).
    for (int item = tid; item < IW * 8; item += 384) {
        int yy = item >> 3;
        int xg = (item & 7) << 2;
        float2 aMU[4], aCV[4]; float aP[4];
        #pragma unroll
        for (int o = 0; o < 4; ++o) {
            aMU[o] = make_float2(0.f, 0.f); aCV[o] = make_float2(0.f, 0.f); aP[o] = 0.f;
        }
        #pragma unroll
        for (int t = 0; t < 14; ++t) {
            float2 ab = sAB[yy][xg + t];
            float2 sq = fmul2(ab, ab);
            float  p  = ab.x * ab.y;
            #pragma unroll
            for (int o = 0; o < 4; ++o) {
                if (o >= t - 10 && o <= t) {
                    aMU[o] = ffma2(w2[t - o], ab, aMU[o]);
                    aCV[o] = ffma2(w2[t - o], sq, aCV[o]);
                    aP[o]  = fmaf(w[t - o], p, aP[o]);
                }
            }
        }
        #pragma unroll
        for (int o = 0; o < 4; ++o) {
            sMU[yy][xg + o] = aMU[o];
            sCV[yy][xg + o] = aCV[o];
            sC12[yy][xg + o] = aP[o];
        }
    }
    __syncthreads();

    // Stage 2: y-conv -> global. 384 items exactly: 3 field-groups x 32 x x 4 ygroups.
    {
        int grp = tid >> 7;                 // 0: MU, 1: CV, 2: C12
        int x   = tid & 31;
        int yg  = ((tid >> 5) & 3) << 3;    // 0,8,16,24
        size_t e0 = base + (size_t)(ty * TILE + yg) * WW + (size_t)(tx * TILE) + x;

        if (grp == 0) {
            float2 acc[8];
            #pragma unroll
            for (int o = 0; o < 8; ++o) acc[o] = make_float2(0.f, 0.f);
            #pragma unroll
            for (int t = 0; t < 18; ++t) {
                float2 v = sMU[yg + t][x];
                #pragma unroll
                for (int o = 0; o < 8; ++o)
                    if (o >= t - 10 && o <= t) acc[o] = ffma2(w2[t - o], v, acc[o]);
            }
            #pragma unroll
            for (int o = 0; o < 8; ++o) g_mu[e0 + (size_t)o * WW] = acc[o];
        } else if (grp == 1) {
            float2 acc[8];
            #pragma unroll
            for (int o = 0; o < 8; ++o) acc[o] = make_float2(0.f, 0.f);
            #pragma unroll
            for (int t = 0; t < 18; ++t) {
                float2 v = sCV[yg + t][x];
                #pragma unroll
                for (int o = 0; o < 8; ++o)
                    if (o >= t - 10 && o <= t) acc[o] = ffma2(w2[t - o], v, acc[o]);
            }
            #pragma unroll
            for (int o = 0; o < 8; ++o) g_cv[e0 + (size_t)o * WW] = acc[o];
        } else {
            float acc[8];
            #pragma unroll
            for (int o = 0; o < 8; ++o) acc[o] = 0.f;
            #pragma unroll
            for (int t = 0; t < 18; ++t) {
                float v = sC12[yg + t][x];
                #pragma unroll
                for (int o = 0; o < 8; ++o)
                    if (o >= t - 10 && o <= t) acc[o] = fmaf(w[t - o], v, acc[o]);
            }
            #pragma unroll
            for (int o = 0; o < 8; ++o) g_c12[e0 + (size_t)o * WW] = acc[o];
        }
    }
}

// ---------------------------------------------------------------------------
// K2: z-conv (static ring via 11x unroll) + SSIM map + reduction + finalize.
// One block = one (b, y) line of 128 x-columns, streaming all z.
// ---------------------------------------------------------------------------
__global__ __launch_bounds__(128) void conv_z_ssim_kernel(float* __restrict__ out)
{
    const int x = threadIdx.x;
    const int y = blockIdx.x;    // 0..127
    const int b = blockIdx.y;    // 0..3
    const size_t col = (size_t)b * VOL + (size_t)y * WW + x;

    float w[WS]; float2 w2[WS];
    #pragma unroll
    for (int t = 0; t < WS; ++t) { w[t] = g_w[t]; w2[t] = make_float2(w[t], w[t]); }

    // Ring slot s holds plane p with (p + 5) % 11 == s. Preload planes -5..5.
    float2 rMU[WS], rCV[WS]; float rP[WS];
    #pragma unroll
    for (int s = 0; s < WS; ++s) {
        int p = s - RAD;
        bool ok = (unsigned)p < DD;
        size_t idx = col + (size_t)(ok ? p : 0) * SLICE;
        rMU[s] = ok ? g_mu[idx]  : make_float2(0.f, 0.f);
        rCV[s] = ok ? g_cv[idx]  : make_float2(0.f, 0.f);
        rP[s]  = ok ? g_c12[idx] : 0.f;
    }

    float fsum = 0.f;
    for (int zb = 0; zb < 132; zb += 11) {
        #pragma unroll
        for (int t2 = 0; t2 < WS; ++t2) {
            const int z = zb + t2;
            float2 mu = make_float2(0.f, 0.f), cv = make_float2(0.f, 0.f);
            float p = 0.f;
            #pragma unroll
            for (int s = 0; s < WS; ++s) {
                const int wi = (s - t2 + WS) % WS;   // compile-time constant
                mu = ffma2(w2[wi], rMU[s], mu);
                cv = ffma2(w2[wi], rCV[s], cv);
                p  = fmaf(w[wi], rP[s], p);
            }
            float2 musq = fmul2(mu, mu);
            float mu12 = mu.x * mu.y;
            float ssum2 = (cv.x - musq.x) + (cv.y - musq.y);
            float s12 = p - mu12;
            float num = (2.f * mu12 + C1F) * (2.f * s12 + C2F);
            float den = (musq.x + musq.y + C1F) * (ssum2 + C2F);
            float v = __fdividef(num, den);
            if (z < DD) fsum += v;

            // Load plane z+6 into slot t2 (slot of plane z+6 == z % 11 == t2).
            int zp = z + RAD + 1;
            bool ok = zp < DD;
            size_t idx = col + (size_t)(ok ? zp : 0) * SLICE;
            rMU[t2] = ok ? g_mu[idx]  : make_float2(0.f, 0.f);
            rCV[t2] = ok ? g_cv[idx]  : make_float2(0.f, 0.f);
            rP[t2]  = ok ? g_c12[idx] : 0.f;
        }
    }

    // Block reduction -> global double accumulator -> last block finalizes.
    double dsum = (double)fsum;
    #pragma unroll
    for (int off = 16; off > 0; off >>= 1)
        dsum += __shfl_down_sync(0xffffffffu, dsum, off);

    __shared__ double ssm[4];
    int wid = threadIdx.x >> 5, lid = threadIdx.x & 31;
    if (lid == 0) ssm[wid] = dsum;
    __syncthreads();
    if (threadIdx.x == 0) {
        double tot = ssm[0] + ssm[1] + ssm[2] + ssm[3];
        atomicAdd(&g_acc, tot);
        __threadfence();
        unsigned done = atomicAdd(&g_cnt, 1u);
        if (done == (unsigned)(HH * BATCH - 1)) {
            out[0] = (float)(g_acc * (1.0 / (double)VTOT));
            g_cnt = 0;   // reset for next graph replay
        }
    }
}

// ---------------------------------------------------------------------------
extern "C" void kernel_launch(void* const* d_in, const int* in_sizes, int n_in,
                              void* d_out, int out_size) {
    (void)in_sizes; (void)n_in; (void)out_size;
    const float* img1   = (const float*)d_in[0];
    const float* img2   = (const float*)d_in[1];
    const float* window = (const float*)d_in[2];

    dim3 g1(WW / TILE, HH / TILE, BATCH * DD);   // (4, 4, 512)
    conv_xy_kernel<<<g1, 384>>>(img1, img2, window);

    dim3 g2(HH, BATCH);                          // (128, 4)
    conv_z_ssim_kernel<<<g2, 128>>>((float*)d_out);
}

// round 3
// speedup vs baseline: 1.1639x; 1.1639x over previous
#include <cuda_runtime.h>

// Problem constants
#define BATCH 4
#define DD 128
#define HH 128
#define WW 128
#define SLICE (HH*WW)          // 16384
#define VOL   (DD*HH*WW)       // 2097152
#define VTOT  (BATCH*VOL)      // 8388608
#define WS 11
#define RAD 5

#define C1F 1.0e-4f            // 0.01^2
#define C2F 9.0e-4f            // 0.03^2

// Packed intermediates: (mu1,mu2) pairs, (E[x^2],E[y^2]) pairs, E[xy] scalar.
__device__ float2 g_mu [VTOT];
__device__ float2 g_cv [VTOT];
__device__ float  g_c12[VTOT];
__device__ float  g_w[WS];
__device__ double g_acc;
__device__ unsigned g_cnt;

// ---------------------------------------------------------------------------
// Packed f32x2 helpers (Blackwell fma.rn.f32x2 / mul.rn.f32x2)
// ---------------------------------------------------------------------------
__device__ __forceinline__ float2 ffma2(float2 a, float2 b, float2 c) {
    float2 d;
    asm("fma.rn.f32x2 %0, %1, %2, %3;"
        : "=l"(reinterpret_cast<unsigned long long&>(d))
        : "l"(reinterpret_cast<unsigned long long&>(a)),
          "l"(reinterpret_cast<unsigned long long&>(b)),
          "l"(reinterpret_cast<unsigned long long&>(c)));
    return d;
}
__device__ __forceinline__ float2 fmul2(float2 a, float2 b) {
    float2 d;
    asm("mul.rn.f32x2 %0, %1, %2;"
        : "=l"(reinterpret_cast<unsigned long long&>(d))
        : "l"(reinterpret_cast<unsigned long long&>(a)),
          "l"(reinterpret_cast<unsigned long long&>(b)));
    return d;
}

// ---------------------------------------------------------------------------
// K1: fused x-conv + y-conv over 32x32 tiles of one (b,z) slice.
// 256 threads, <=43KB smem -> 4 blocks/SM (reg cap 64).
// ---------------------------------------------------------------------------
#define TILE 32
#define IW   42   // TILE + 2*RAD
#define ABS  43   // sAB row stride (float2): conflict-free for stage-1 pattern
#define INS  33   // intermediate row stride

__global__ __launch_bounds__(256, 4) void conv_xy_kernel(
    const float* __restrict__ img1, const float* __restrict__ img2,
    const float* __restrict__ window)
{
    __shared__ float2 sAB[IW][ABS];       // 14448 B
    __shared__ float2 sMU[IW][INS];       // 11088 B
    __shared__ float2 sCV[IW][INS];       // 11088 B
    __shared__ float  sP [IW][INS];       //  5544 B
    __shared__ float2 sw2[WS];

    const int tid = threadIdx.x;
    const int tx = blockIdx.x, ty = blockIdx.y, bz = blockIdx.z; // bz = b*128+z
    const int x0 = tx * TILE - RAD;
    const int y0 = ty * TILE - RAD;
    const size_t base = (size_t)bz * SLICE;

    // Recover separable 1-D Gaussian: row sums of the 3-D window are exact.
    if (tid < WS) {
        float s = 0.f;
        #pragma unroll 11
        for (int j = 0; j < 121; ++j) s += __ldg(window + tid * 121 + j);
        sw2[tid] = make_float2(s, s);
        if (bz == 0 && tx == 0 && ty == 0) {
            g_w[tid] = s;                 // for K2
            if (tid == 0) g_acc = 0.0;    // graph-replay safe (K2 runs after K1)
        }
    }

    // Load 42x42 interleaved (a,b) halo tile (zero-pad outside volume).
    for (int i = tid; i < IW * IW; i += 256) {
        int yy = i / IW, xx = i - yy * IW;
        int gy = y0 + yy, gx = x0 + xx;
        float a = 0.f, b = 0.f;
        if ((unsigned)gy < HH && (unsigned)gx < WW) {
            size_t idx = base + (size_t)gy * WW + gx;
            a = __ldg(img1 + idx);
            b = __ldg(img2 + idx);
        }
        sAB[yy][xx] = make_float2(a, b);
    }
    __syncthreads();

    // Stage 1: x-conv. 336 items = 42 rows x 8 groups of 4 outputs.
    for (int item = tid; item < IW * 8; item += 256) {
        int yy = item >> 3;
        int xg = (item & 7) << 2;
        float2 aMU[4], aCV[4]; float aP[4];
        #pragma unroll
        for (int o = 0; o < 4; ++o) {
            aMU[o] = make_float2(0.f, 0.f);
            aCV[o] = make_float2(0.f, 0.f);
            aP[o]  = 0.f;
        }
        #pragma unroll
        for (int t = 0; t < 14; ++t) {
            float2 ab = sAB[yy][xg + t];
            float2 sq = fmul2(ab, ab);
            float  p  = ab.x * ab.y;
            #pragma unroll
            for (int o = 0; o < 4; ++o) {
                const int k = t - o;
                if (k >= 0 && k <= 10) {
                    float2 wv = sw2[k];
                    aMU[o] = ffma2(wv, ab, aMU[o]);
                    aCV[o] = ffma2(wv, sq, aCV[o]);
                    aP[o]  = fmaf(wv.x, p, aP[o]);
                }
            }
        }
        #pragma unroll
        for (int o = 0; o < 4; ++o) {
            sMU[yy][xg + o] = aMU[o];
            sCV[yy][xg + o] = aCV[o];
            sP [yy][xg + o] = aP[o];
        }
    }
    __syncthreads();

    // Stage 2: y-conv -> global. 384 items: field(3) x x(32) x ygroup(4 of 8).
    for (int i = tid; i < 384; i += 256) {
        int f  = i >> 7;
        int x  = i & 31;
        int yg = ((i >> 5) & 3) << 3;
        size_t e0 = base + (size_t)(ty * TILE + yg) * WW + (size_t)(tx * TILE) + x;

        if (f == 0) {
            float2 acc[8];
            #pragma unroll
            for (int o = 0; o < 8; ++o) acc[o] = make_float2(0.f, 0.f);
            #pragma unroll
            for (int t = 0; t < 18; ++t) {
                float2 v = sMU[yg + t][x];
                #pragma unroll
                for (int o = 0; o < 8; ++o) {
                    const int k = t - o;
                    if (k >= 0 && k <= 10) acc[o] = ffma2(sw2[k], v, acc[o]);
                }
            }
            #pragma unroll
            for (int o = 0; o < 8; ++o) g_mu[e0 + (size_t)o * WW] = acc[o];
        } else if (f == 1) {
            float2 acc[8];
            #pragma unroll
            for (int o = 0; o < 8; ++o) acc[o] = make_float2(0.f, 0.f);
            #pragma unroll
            for (int t = 0; t < 18; ++t) {
                float2 v = sCV[yg + t][x];
                #pragma unroll
                for (int o = 0; o < 8; ++o) {
                    const int k = t - o;
                    if (k >= 0 && k <= 10) acc[o] = ffma2(sw2[k], v, acc[o]);
                }
            }
            #pragma unroll
            for (int o = 0; o < 8; ++o) g_cv[e0 + (size_t)o * WW] = acc[o];
        } else {
            float acc[8];
            #pragma unroll
            for (int o = 0; o < 8; ++o) acc[o] = 0.f;
            #pragma unroll
            for (int t = 0; t < 18; ++t) {
                float v = sP[yg + t][x];
                #pragma unroll
                for (int o = 0; o < 8; ++o) {
                    const int k = t - o;
                    if (k >= 0 && k <= 10) acc[o] = fmaf(sw2[k].x, v, acc[o]);
                }
            }
            #pragma unroll
            for (int o = 0; o < 8; ++o) g_c12[e0 + (size_t)o * WW] = acc[o];
        }
    }
}

// ---------------------------------------------------------------------------
// K2: z-conv + SSIM + reduction + finalize. 2048 blocks x 128 threads.
// Ring in registers with compile-time slots; depth-4 prefetch for MLP.
// ---------------------------------------------------------------------------
struct Plane { float2 mu, cv; float p; };

__device__ __forceinline__ Plane load_plane(size_t col, int zz) {
    Plane r;
    bool ok = (unsigned)zz < DD;
    size_t idx = col + (size_t)(ok ? zz : 0) * SLICE;
    r.mu = ok ? g_mu[idx]  : make_float2(0.f, 0.f);
    r.cv = ok ? g_cv[idx]  : make_float2(0.f, 0.f);
    r.p  = ok ? g_c12[idx] : 0.f;
    return r;
}

__global__ __launch_bounds__(128, 4) void conv_z_ssim_kernel(float* __restrict__ out)
{
    const int x  = threadIdx.x;
    const int zc = blockIdx.x;   // z-chunk of 32: 0..3
    const int y  = blockIdx.y;   // 0..127
    const int b  = blockIdx.z;   // 0..3
    const int z0 = zc * 32;
    const size_t col = (size_t)b * VOL + (size_t)y * WW + x;

    float2 w2[WS];
    #pragma unroll
    for (int t = 0; t < WS; ++t) { float ww = g_w[t]; w2[t] = make_float2(ww, ww); }

    // Ring: slot s initially holds relative plane s-5.
    Plane ring[WS];
    #pragma unroll
    for (int s = 0; s < WS; ++s) ring[s] = load_plane(col, z0 + s - RAD);

    // Prefetch pipeline, depth 4: buffers hold relative planes 6..9.
    Plane pf[4];
    #pragma unroll
    for (int q = 0; q < 4; ++q) pf[q] = load_plane(col, z0 + RAD + 1 + q);

    float fsum = 0.f;
    #pragma unroll
    for (int oz = 0; oz < 33; ++oz) {   // 33 = 3*11 so slot math is compile-time
        float2 mu = make_float2(0.f, 0.f), cv = make_float2(0.f, 0.f);
        float p = 0.f;
        #pragma unroll
        for (int s = 0; s < WS; ++s) {
            const int wi = ((s - oz) % WS + WS) % WS;   // compile-time
            mu = ffma2(w2[wi], ring[s].mu, mu);
            cv = ffma2(w2[wi], ring[s].cv, cv);
            p  = fmaf(w2[wi].x, ring[s].p, p);
        }
        float2 musq = fmul2(mu, mu);
        float mu12  = mu.x * mu.y;
        float svar  = (cv.x - musq.x) + (cv.y - musq.y);
        float s12   = p - mu12;
        float num = (2.f * mu12 + C1F) * (2.f * s12 + C2F);
        float den = (musq.x + musq.y + C1F) * (svar + C2F);
        float v = __fdividef(num, den);
        if (oz < 32) fsum += v;

        // Insert prefetched plane oz+6 (slot oz%11), refill buffer with oz+10.
        ring[oz % WS] = pf[oz & 3];
        pf[oz & 3] = load_plane(col, z0 + oz + RAD + 5);
    }

    // Block reduction -> global double accumulator -> last block finalizes.
    double dsum = (double)fsum;
    #pragma unroll
    for (int off = 16; off > 0; off >>= 1)
        dsum += __shfl_down_sync(0xffffffffu, dsum, off);

    __shared__ double ssm[4];
    int wid = threadIdx.x >> 5, lid = threadIdx.x & 31;
    if (lid == 0) ssm[wid] = dsum;
    __syncthreads();
    if (threadIdx.x == 0) {
        double tot = ssm[0] + ssm[1] + ssm[2] + ssm[3];
        atomicAdd(&g_acc, tot);
        __threadfence();
        unsigned done = atomicAdd(&g_cnt, 1u);
        if (done == (unsigned)(4 * HH * BATCH - 1)) {
            out[0] = (float)(g_acc * (1.0 / (double)VTOT));
            g_cnt = 0;   // reset for next graph replay
        }
    }
}

// ---------------------------------------------------------------------------
extern "C" void kernel_launch(void* const* d_in, const int* in_sizes, int n_in,
                              void* d_out, int out_size) {
    (void)in_sizes; (void)n_in; (void)out_size;
    const float* img1   = (const float*)d_in[0];
    const float* img2   = (const float*)d_in[1];
    const float* window = (const float*)d_in[2];

    dim3 g1(WW / TILE, HH / TILE, BATCH * DD);   // (4, 4, 512)
    conv_xy_kernel<<<g1, 256>>>(img1, img2, window);

    dim3 g2(DD / 32, HH, BATCH);                 // (4, 128, 4) = 2048 blocks
    conv_z_ssim_kernel<<<g2, 128>>>((float*)d_out);
}